// round 12
// baseline (speedup 1.0000x reference)
#include <cuda_runtime.h>
#include <cstdint>

// HashGrid trilinear interpolation + gradient, GB300 sm_103a.
//   d_in[0]: x           (N,3)        float32   N = in_sizes[0]/3
//   d_in[1]: feat_params (CAP,520,5)  float32
//   d_in[2]: block_table (32,32,32)   int32
// Output: concat [feats (N,5) | dfeats_dx (N,5,3) | masks (N)] float32.
//
// 2 lanes per point split by cz (lane&1). Pipeline depth 2 per warp with ZERO
// carried B-state: phase 1 sets up group B and fires cp.async.cg into smem
// (temps die), phase 2/3 = R9 (register loads + consume + store for A),
// phase 4 waits and RECOMPUTES B's setup (L1-hot x/btab via laundered
// pointers to defeat CSE) before consuming from smem.

#define RR 8
#define GG 32
#define FF 5
#define STRIDE_ 520
#define INV_V 100.0f   // 1/0.01f == 100.0f exactly; XLA folds x/V -> x*INV_V

static __device__ __forceinline__ void setup_point(
    const float* __restrict__ x, const int* __restrict__ btab,
    int ic, int half,
    int e[4], bool& okh, float& fx, float& fy, float& fz)
{
    float ux = x[3 * ic + 0] * INV_V;
    float uy = x[3 * ic + 1] * INV_V;
    float uz = x[3 * ic + 2] * INV_V;
    float fux = floorf(ux), fuy = floorf(uy), fuz = floorf(uz);
    int xi0 = (int)fux, yi0 = (int)fuy, zi0 = (int)fuz;
    fx = ux - fux; fy = uy - fuy; fz = uz - fuz;

    int lx0 = xi0 & 7, ly0 = yi0 & 7, lz0 = zi0 & 7;
    int bx0 = xi0 >> 3, by0 = yi0 >> 3, bz0 = zi0 >> 3;

    bool fast = (lx0 < 7) & (ly0 < 7) & (lz0 < 7) &
                ((unsigned)bx0 < GG) & ((unsigned)by0 < GG) & ((unsigned)bz0 < GG);
    if (fast) {
        int b = __ldg(&btab[(bx0 * GG + by0) * GG + bz0]);
        okh = (b >= 0);
        int base = (max(b, 0) * STRIDE_ + (lx0 * RR + ly0) * RR + lz0 + half) * FF;
        e[0] = base;             // cx=0 cy=0
        e[1] = base + 8 * FF;    // cx=0 cy=1
        e[2] = base + 64 * FF;   // cx=1 cy=0
        e[3] = base + 72 * FF;   // cx=1 cy=1
    } else {
        okh = true;
#pragma unroll
        for (int c = 0; c < 4; ++c) {
            int cx = (c >> 1) & 1, cy = c & 1;
            int gx = xi0 + cx, gy = yi0 + cy, gz = zi0 + half;
            int bx = gx >> 3, by = gy >> 3, bz = gz >> 3;
            int lx = gx & 7,  ly = gy & 7,  lz = gz & 7;
            bool inb = ((unsigned)bx < GG) & ((unsigned)by < GG) & ((unsigned)bz < GG);
            int b = -1;
            if (inb) b = __ldg(&btab[(bx * GG + by) * GG + bz]);
            okh &= inb & (b >= 0);
            e[c] = (max(b, 0) * STRIDE_ + (lx * RR + ly) * RR + lz) * FF;
        }
    }
}

// Accumulate one corner's contribution given its two 16B-aligned float4s.
static __device__ __forceinline__ void corner_accum(
    float4 ra, float4 rb, int s, int c,
    float fx, float fy, float ox, float oy, float pzw, float sz,
    float acc[FF], float gax[FF], float gay[FF], float gaz[FF])
{
    bool hi = (s & 2) != 0;
    float b0 = hi ? ra.z : ra.x;
    float b1 = hi ? ra.w : ra.y;
    float b2 = hi ? rb.x : ra.z;
    float b3 = hi ? rb.y : ra.w;
    float b4 = hi ? rb.z : rb.x;
    float b5 = hi ? rb.w : rb.y;
    bool od = (s & 1) != 0;
    float v0 = od ? b1 : b0;
    float v1 = od ? b2 : b1;
    float v2 = od ? b3 : b2;
    float v3 = od ? b4 : b3;
    float v4 = od ? b5 : b4;

    int cx = (c >> 1) & 1, cy = c & 1;
    float pxw = cx ? fx : ox;
    float pyw = cy ? fy : oy;
    float sx  = cx ? 1.0f : -1.0f;
    float sy  = cy ? 1.0f : -1.0f;
    float w   = pxw * pyw * pzw;
    float dwx = sx * pyw * pzw;
    float dwy = pxw * sy * pzw;
    float dwz = pxw * pyw * sz;
    acc[0] += w * v0;  acc[1] += w * v1;  acc[2] += w * v2;
    acc[3] += w * v3;  acc[4] += w * v4;
    gax[0] += dwx * v0; gax[1] += dwx * v1; gax[2] += dwx * v2;
    gax[3] += dwx * v3; gax[4] += dwx * v4;
    gay[0] += dwy * v0; gay[1] += dwy * v1; gay[2] += dwy * v2;
    gay[3] += dwy * v3; gay[4] += dwy * v4;
    gaz[0] += dwz * v0; gaz[1] += dwz * v1; gaz[2] += dwz * v2;
    gaz[3] += dwz * v3; gaz[4] += dwz * v4;
}

// Pair-reduce + stage + coalesced streaming stores for a 16-point group.
static __device__ __forceinline__ void reduce_store_group(
    float* __restrict__ out, size_t n_sz, int n, int gp0,
    int lane, int pl, int half, float* sw, bool ok,
    float acc[FF], float gax[FF], float gay[FF], float gaz[FF])
{
#pragma unroll
    for (int f = 0; f < FF; ++f) {
        acc[f] += __shfl_xor_sync(0xFFFFFFFFu, acc[f], 1);
        gax[f] += __shfl_xor_sync(0xFFFFFFFFu, gax[f], 1);
        gay[f] += __shfl_xor_sync(0xFFFFFFFFu, gay[f], 1);
        gaz[f] += __shfl_xor_sync(0xFFFFFFFFu, gaz[f], 1);
    }
    int i = gp0 + pl;
    bool valid = (i < n);
    if (valid && half == 0)
        __stcs(out + n_sz * (FF + FF * 3) + i, ok ? 1.0f : 0.0f);

    bool full = (gp0 + 16 <= n);
    if (full) {
        if (half == 0) {
#pragma unroll
            for (int f = 0; f < FF; ++f) sw[pl * FF + f] = acc[f];
        }
        __syncwarp();
        {   // feats: 16*5 = 80 floats = 20 float4
            const float4* src = (const float4*)sw;
            float4* dst = (float4*)(out + (size_t)gp0 * FF);
            if (lane < 20) __stcs(dst + lane, src[lane]);
        }
        __syncwarp();
        if (half == 1) {
#pragma unroll
            for (int f = 0; f < FF; ++f) {
                sw[pl * 15 + f * 3 + 0] = gax[f] * INV_V;
                sw[pl * 15 + f * 3 + 1] = gay[f] * INV_V;
                sw[pl * 15 + f * 3 + 2] = gaz[f] * INV_V;
            }
        }
        __syncwarp();
        {   // dfeats: 16*15 = 240 floats = 60 float4
            const float4* src = (const float4*)sw;
            float4* dst = (float4*)(out + n_sz * FF + (size_t)gp0 * 15);
            __stcs(dst + lane, src[lane]);
            if (lane < 28) __stcs(dst + lane + 32, src[lane + 32]);
        }
        __syncwarp();
    } else if (valid && half == 0) {
        // tail fallback (unused: n % 32 == 0 for N=2M)
#pragma unroll
        for (int f = 0; f < FF; ++f) out[(size_t)i * FF + f] = acc[f];
        float* dfe = out + n_sz * FF + (size_t)i * 15;
#pragma unroll
        for (int f = 0; f < FF; ++f) {
            dfe[f * 3 + 0] = gax[f] * INV_V;
            dfe[f * 3 + 1] = gay[f] * INV_V;
            dfe[f * 3 + 2] = gaz[f] * INV_V;
        }
    }
}

__global__ void __launch_bounds__(256)
hashgrid_kernel(const float* __restrict__ x,
                const float* __restrict__ feat,
                const int*   __restrict__ btab,
                float* __restrict__ out,
                int n)
{
    // cp.async landing buffer for group B: [warp][chunk][lane]; LDS.128 by
    // chunk is conflict-free (16B lane stride). 8 warps * 4KB = 32KB.
    __shared__ __align__(16) float4 bufB[8][8][32];
    __shared__ __align__(16) float  stage[8][16 * 15];

    int lane    = threadIdx.x & 31;
    int warp    = threadIdx.x >> 5;
    int warp_p0 = blockIdx.x * 256 + warp * 32;   // 32 points per warp
    if (warp_p0 >= n) return;
    int pl   = lane >> 1;
    int half = lane & 1;
    size_t n_sz = (size_t)n;
    float* sw = stage[warp];

    int iA = warp_p0 + pl;
    int iB = warp_p0 + 16 + pl;

    // ---- phase 1: group B setup + cp.async (all temporaries die here) ----
    bool okB;
    {
        int eB[4]; bool okhB; float t0, t1, t2;
        setup_point(x, btab, iB < n ? iB : n - 1, half, eB, okhB, t0, t1, t2);
        okhB &= (iB < n);
        okB = okhB & (bool)__shfl_xor_sync(0xFFFFFFFFu, (unsigned)okhB, 1);
        if (okB) {
#pragma unroll
            for (int c = 0; c < 4; ++c) {
                const char* src = (const char*)feat + (((size_t)eB[c] * 4) & ~(size_t)15);
                uint32_t d0 = (uint32_t)__cvta_generic_to_shared(&bufB[warp][2 * c][lane]);
                uint32_t d1 = (uint32_t)__cvta_generic_to_shared(&bufB[warp][2 * c + 1][lane]);
                asm volatile("cp.async.cg.shared.global [%0], [%1], 16;\n"
                             :: "r"(d0), "l"(src));
                asm volatile("cp.async.cg.shared.global [%0], [%1], 16;\n"
                             :: "r"(d1), "l"(src + 16));
            }
        }
        asm volatile("cp.async.commit_group;\n");
    }

    // ---- phase 2: group A setup + register loads (== R9 body) ----
    int eA[4]; bool okhA; float fxA, fyA, fzA;
    setup_point(x, btab, iA < n ? iA : n - 1, half, eA, okhA, fxA, fyA, fzA);
    okhA &= (iA < n);
    bool okA = okhA & (bool)__shfl_xor_sync(0xFFFFFFFFu, (unsigned)okhA, 1);
    float4 raA[4], rbA[4];
    if (okA) {
#pragma unroll
        for (int c = 0; c < 4; ++c) {
            const float4* p = (const float4*)((const char*)feat +
                                              (((size_t)eA[c] * 4) & ~(size_t)15));
            raA[c] = __ldg(p);
            rbA[c] = __ldg(p + 1);
        }
    }

    // ---- phase 3: consume + store A (B's cp.asyncs in flight) ----
    {
        float acc[FF] = {0, 0, 0, 0, 0};
        float gax[FF] = {0, 0, 0, 0, 0};
        float gay[FF] = {0, 0, 0, 0, 0};
        float gaz[FF] = {0, 0, 0, 0, 0};
        if (okA) {
            float ox = 1.0f - fxA, oy = 1.0f - fyA, oz = 1.0f - fzA;
            float pzw = half ? fzA : oz;
            float sz  = half ? 1.0f : -1.0f;
#pragma unroll
            for (int c = 0; c < 4; ++c)
                corner_accum(raA[c], rbA[c], eA[c] & 3, c,
                             fxA, fyA, ox, oy, pzw, sz, acc, gax, gay, gaz);
        }
        reduce_store_group(out, n_sz, n, warp_p0, lane, pl, half, sw, okA,
                           acc, gax, gay, gaz);
    }

    // ---- phase 4: wait, RECOMPUTE B setup (L1-hot), consume from smem ----
    asm volatile("cp.async.wait_group 0;\n");
    {
        // laundered pointers: block CSE with phase-1 setup so B's fracs are
        // not kept live across phases 2-3
        const float* x2 = x;   asm("" : "+l"(x2));
        const int*   bt2 = btab; asm("" : "+l"(bt2));
        int eB[4]; bool okhB; float fxB, fyB, fzB;
        setup_point(x2, bt2, iB < n ? iB : n - 1, half, eB, okhB, fxB, fyB, fzB);

        float acc[FF] = {0, 0, 0, 0, 0};
        float gax[FF] = {0, 0, 0, 0, 0};
        float gay[FF] = {0, 0, 0, 0, 0};
        float gaz[FF] = {0, 0, 0, 0, 0};
        if (okB) {
            float ox = 1.0f - fxB, oy = 1.0f - fyB, oz = 1.0f - fzB;
            float pzw = half ? fzB : oz;
            float sz  = half ? 1.0f : -1.0f;
#pragma unroll
            for (int c = 0; c < 4; ++c) {
                float4 ra = bufB[warp][2 * c][lane];
                float4 rb = bufB[warp][2 * c + 1][lane];
                corner_accum(ra, rb, eB[c] & 3, c,
                             fxB, fyB, ox, oy, pzw, sz, acc, gax, gay, gaz);
            }
        }
        reduce_store_group(out, n_sz, n, warp_p0 + 16, lane, pl, half, sw, okB,
                           acc, gax, gay, gaz);
    }
}

extern "C" void kernel_launch(void* const* d_in, const int* in_sizes, int n_in,
                              void* d_out, int out_size)
{
    const float* x    = (const float*)d_in[0];
    const float* feat = (const float*)d_in[1];
    const int*   btab = (const int*)d_in[2];
    float*       out  = (float*)d_out;

    int n = in_sizes[0] / 3;
    int threads = 256;                       // 256 points per block
    int blocks = (n + 255) / 256;
    hashgrid_kernel<<<blocks, threads>>>(x, feat, btab, out, n);
}

// round 13
// speedup vs baseline: 1.3000x; 1.3000x over previous
#include <cuda_runtime.h>
#include <cstdint>

// HashGrid trilinear interpolation + gradient, GB300 sm_103a.
//   d_in[0]: x           (N,3)        float32   N = in_sizes[0]/3
//   d_in[1]: feat_params (CAP,520,5)  float32
//   d_in[2]: block_table (32,32,32)   int32
// Output: concat [feats (N,5) | dfeats_dx (N,5,3) | masks (N)] float32.
//
// R9 structure (best: 113us): 2 lanes per point split by cz (lane&1) so the
// pair's records (20B apart) share L1 lines; 8 LDG.128 per lane batched
// back-to-back; pair reduce via shfl_xor(1); warp-staged coalesced float4
// streaming stores.
// R13 delta: feature gathers carry an L2::evict_last cache-hint policy so
// feat lines survive the streaming output traffic (208MB table vs 126MB L2;
// measured L2 hit rate ~0 without the hint).

#define RR 8
#define GG 32
#define FF 5
#define STRIDE_ 520
#define INV_V 100.0f   // 1/0.01f == 100.0f exactly; XLA folds x/V -> x*INV_V

static __device__ __forceinline__ float4 ldg_el(const void* p, uint64_t pol)
{
    float4 r;
    asm volatile("ld.global.nc.L2::cache_hint.v4.f32 {%0,%1,%2,%3}, [%4], %5;"
                 : "=f"(r.x), "=f"(r.y), "=f"(r.z), "=f"(r.w)
                 : "l"(p), "l"(pol));
    return r;
}

__global__ void __launch_bounds__(256)
hashgrid_kernel(const float* __restrict__ x,
                const float* __restrict__ feat,
                const int*   __restrict__ btab,
                float* __restrict__ out,
                int n)
{
    // per-warp staging: 16 points * 15 floats (reused feats -> dfeats)
    __shared__ __align__(16) float stage[8][16 * 15];

    int lane    = threadIdx.x & 31;
    int warp    = threadIdx.x >> 5;
    int warp_p0 = blockIdx.x * 128 + warp * 16;   // 16 points per warp
    if (warp_p0 >= n) return;
    int pl   = lane >> 1;          // point slot in warp: 0..15
    int half = lane & 1;           // cz for this lane's 4 corners
    int i = warp_p0 + pl;
    bool valid = (i < n);
    int ic = valid ? i : (n - 1);

    // L2 evict_last policy for feature gathers
    uint64_t pol;
    asm volatile("createpolicy.fractional.L2::evict_last.b64 %0, 1.0;" : "=l"(pol));

    // ---- cell + frac (bit-exact: multiply by reciprocal like XLA) ----
    float ux = x[3 * ic + 0] * INV_V;
    float uy = x[3 * ic + 1] * INV_V;
    float uz = x[3 * ic + 2] * INV_V;
    float fux = floorf(ux), fuy = floorf(uy), fuz = floorf(uz);
    int xi0 = (int)fux, yi0 = (int)fuy, zi0 = (int)fuz;
    float fx = ux - fux, fy = uy - fuy, fz = uz - fuz;

    int lx0 = xi0 & 7, ly0 = yi0 & 7, lz0 = zi0 & 7;
    int bx0 = xi0 >> 3, by0 = yi0 >> 3, bz0 = zi0 >> 3;

    bool fast = (lx0 < 7) & (ly0 < 7) & (lz0 < 7) &
                ((unsigned)bx0 < GG) & ((unsigned)by0 < GG) & ((unsigned)bz0 < GG);

    // ---- this lane's 4 record element-offsets (corners (cx,cy), cz=half) ----
    int  e[4];
    bool okh;
    if (fast) {
        int b = __ldg(&btab[(bx0 * GG + by0) * GG + bz0]);
        okh = (b >= 0);
        int base = (max(b, 0) * STRIDE_ + (lx0 * RR + ly0) * RR + lz0 + half) * FF;
        e[0] = base;             // cx=0 cy=0
        e[1] = base + 8 * FF;    // cx=0 cy=1
        e[2] = base + 64 * FF;   // cx=1 cy=0
        e[3] = base + 72 * FF;   // cx=1 cy=1
    } else {
        okh = true;
#pragma unroll
        for (int c = 0; c < 4; ++c) {
            int cx = (c >> 1) & 1, cy = c & 1;
            int gx = xi0 + cx, gy = yi0 + cy, gz = zi0 + half;
            int bx = gx >> 3, by = gy >> 3, bz = gz >> 3;
            int lx = gx & 7,  ly = gy & 7,  lz = gz & 7;
            bool inb = ((unsigned)bx < GG) & ((unsigned)by < GG) & ((unsigned)bz < GG);
            int b = -1;
            if (inb) b = __ldg(&btab[(bx * GG + by) * GG + bz]);
            okh &= inb & (b >= 0);
            e[c] = (max(b, 0) * STRIDE_ + (lx * RR + ly) * RR + lz) * FF;
        }
    }
    okh &= valid;
    bool ok = okh & (bool)__shfl_xor_sync(0xFFFFFFFFu, (unsigned)okh, 1);

    // ---- gather: batch ALL 8 cache-hinted LDG.128 before consuming ----
    float acc[FF] = {0, 0, 0, 0, 0};
    float gax[FF] = {0, 0, 0, 0, 0};
    float gay[FF] = {0, 0, 0, 0, 0};
    float gaz[FF] = {0, 0, 0, 0, 0};
    if (ok) {
        float4 ra[4], rb[4];
#pragma unroll
        for (int c = 0; c < 4; ++c) {
            const char* p = (const char*)feat + (((size_t)e[c] * 4) & ~(size_t)15);
            ra[c] = ldg_el(p, pol);
            rb[c] = ldg_el(p + 16, pol);
        }
        float ox = 1.0f - fx, oy = 1.0f - fy, oz = 1.0f - fz;
        float pzw = half ? fz : oz;
        float sz  = half ? 1.0f : -1.0f;
#pragma unroll
        for (int c = 0; c < 4; ++c) {
            // extract 5 floats from the two aligned float4s
            int s = e[c] & 3;
            bool hi = (s & 2) != 0;
            float b0 = hi ? ra[c].z : ra[c].x;
            float b1 = hi ? ra[c].w : ra[c].y;
            float b2 = hi ? rb[c].x : ra[c].z;
            float b3 = hi ? rb[c].y : ra[c].w;
            float b4 = hi ? rb[c].z : rb[c].x;
            float b5 = hi ? rb[c].w : rb[c].y;
            bool od = (s & 1) != 0;
            float v0 = od ? b1 : b0;
            float v1 = od ? b2 : b1;
            float v2 = od ? b3 : b2;
            float v3 = od ? b4 : b3;
            float v4 = od ? b5 : b4;

            int cx = (c >> 1) & 1, cy = c & 1;
            float pxw = cx ? fx : ox;
            float pyw = cy ? fy : oy;
            float sx  = cx ? 1.0f : -1.0f;
            float sy  = cy ? 1.0f : -1.0f;
            float w   = pxw * pyw * pzw;
            float dwx = sx * pyw * pzw;
            float dwy = pxw * sy * pzw;
            float dwz = pxw * pyw * sz;
            acc[0] += w * v0;  acc[1] += w * v1;  acc[2] += w * v2;
            acc[3] += w * v3;  acc[4] += w * v4;
            gax[0] += dwx * v0; gax[1] += dwx * v1; gax[2] += dwx * v2;
            gax[3] += dwx * v3; gax[4] += dwx * v4;
            gay[0] += dwy * v0; gay[1] += dwy * v1; gay[2] += dwy * v2;
            gay[3] += dwy * v3; gay[4] += dwy * v4;
            gaz[0] += dwz * v0; gaz[1] += dwz * v1; gaz[2] += dwz * v2;
            gaz[3] += dwz * v3; gaz[4] += dwz * v4;
        }
    }

    // ---- pair reduce (butterfly: both lanes end with the full sums) ----
#pragma unroll
    for (int f = 0; f < FF; ++f) {
        acc[f] += __shfl_xor_sync(0xFFFFFFFFu, acc[f], 1);
        gax[f] += __shfl_xor_sync(0xFFFFFFFFu, gax[f], 1);
        gay[f] += __shfl_xor_sync(0xFFFFFFFFu, gay[f], 1);
        gaz[f] += __shfl_xor_sync(0xFFFFFFFFu, gaz[f], 1);
    }

    size_t n_sz = (size_t)n;
    // ---- mask: even lanes write 16 consecutive floats ----
    if (valid && half == 0)
        __stcs(out + n_sz * (FF + FF * 3) + i, ok ? 1.0f : 0.0f);

    float* sw = stage[warp];
    bool full_warp = (warp_p0 + 16 <= n);

    // ---- stage: even lane writes feats (5), odd lane writes dfeats (15) ----
    if (full_warp) {
        if (half == 0) {
#pragma unroll
            for (int f = 0; f < FF; ++f) sw[pl * FF + f] = acc[f];
        }
        __syncwarp();
        {   // feats: 16*5 = 80 floats = 20 float4
            const float4* src = (const float4*)sw;
            float4* dst = (float4*)(out + (size_t)warp_p0 * FF);
            if (lane < 20) __stcs(dst + lane, src[lane]);
        }
        __syncwarp();
        if (half == 1) {
#pragma unroll
            for (int f = 0; f < FF; ++f) {
                sw[pl * 15 + f * 3 + 0] = gax[f] * INV_V;
                sw[pl * 15 + f * 3 + 1] = gay[f] * INV_V;
                sw[pl * 15 + f * 3 + 2] = gaz[f] * INV_V;
            }
        }
        __syncwarp();
        {   // dfeats: 16*15 = 240 floats = 60 float4
            const float4* src = (const float4*)sw;
            float4* dst = (float4*)(out + n_sz * FF + (size_t)warp_p0 * 15);
            __stcs(dst + lane, src[lane]);
            if (lane < 28) __stcs(dst + lane + 32, src[lane + 32]);
        }
    } else if (valid && half == 0) {
        // tail fallback (unused: n % 128 == 0 for N=2M)
#pragma unroll
        for (int f = 0; f < FF; ++f) out[(size_t)i * FF + f] = acc[f];
        float* dfe = out + n_sz * FF + (size_t)i * 15;
#pragma unroll
        for (int f = 0; f < FF; ++f) {
            dfe[f * 3 + 0] = gax[f] * INV_V;
            dfe[f * 3 + 1] = gay[f] * INV_V;
            dfe[f * 3 + 2] = gaz[f] * INV_V;
        }
    }
}

extern "C" void kernel_launch(void* const* d_in, const int* in_sizes, int n_in,
                              void* d_out, int out_size)
{
    const float* x    = (const float*)d_in[0];
    const float* feat = (const float*)d_in[1];
    const int*   btab = (const int*)d_in[2];
    float*       out  = (float*)d_out;

    int n = in_sizes[0] / 3;
    int threads = 256;                       // 128 points per block
    int blocks = (n + 127) / 128;
    hashgrid_kernel<<<blocks, threads>>>(x, feat, btab, out, n);
}